// round 3
// baseline (speedup 1.0000x reference)
#include <cuda_runtime.h>
#include <cuda_bf16.h>
#include <cstdint>
#include <cstddef>

#define N_NODES 50000
#define N_EDGES 800000

// Scratch (allocation-free rule: __device__ globals)
__device__ float g_S[(size_t)N_NODES * 128];  // support = h @ W
__device__ float g_A[(size_t)N_NODES * 128];  // aggregation target / next-layer input

// ---------------------------------------------------------------------------
// GEMM: C[N, DOUT] = act(H)[N, DIN] @ W[DIN, DOUT]
// act = relu on load if RELU (fuses previous layer's relu into this read).
// 64 rows per block, 256 threads, K-tiled smem staging, RPTx4 register tile.
// ---------------------------------------------------------------------------
template <int DIN, int DOUT, bool RELU>
__global__ void __launch_bounds__(256) gemm_kernel(const float* __restrict__ H,
                                                   const float* __restrict__ W,
                                                   float* __restrict__ C, int N) {
    constexpr int KB  = 32;
    constexpr int NC  = DOUT / 4;   // column groups (4 cols each)
    constexpr int NR  = 256 / NC;   // row groups
    constexpr int RPT = 64 / NR;    // rows per thread

    __shared__ float Hs[64 * KB];
    __shared__ float Ws[KB * DOUT];

    const int tid  = threadIdx.x;
    const int row0 = blockIdx.x * 64;
    const int cg   = tid % NC;
    const int rg   = tid / NC;

    float acc[RPT][4];
#pragma unroll
    for (int i = 0; i < RPT; i++) {
        acc[i][0] = 0.f; acc[i][1] = 0.f; acc[i][2] = 0.f; acc[i][3] = 0.f;
    }

    for (int k0 = 0; k0 < DIN; k0 += KB) {
        // stage H tile: 64 rows x KB cols
#pragma unroll
        for (int t = tid; t < 64 * KB / 4; t += 256) {
            int r   = t >> 3;       // KB/4 = 8 float4 per row
            int kk4 = t & 7;
            int row = row0 + r;
            float4 v = make_float4(0.f, 0.f, 0.f, 0.f);
            if (row < N)
                v = *(const float4*)(H + (size_t)row * DIN + k0 + kk4 * 4);
            if (RELU) {
                v.x = fmaxf(v.x, 0.f); v.y = fmaxf(v.y, 0.f);
                v.z = fmaxf(v.z, 0.f); v.w = fmaxf(v.w, 0.f);
            }
            *(float4*)(Hs + r * KB + kk4 * 4) = v;
        }
        // stage W tile: KB rows x DOUT cols
#pragma unroll
        for (int t = tid; t < KB * NC; t += 256) {
            int kk = t / NC;
            int c4 = t % NC;
            *(float4*)(Ws + kk * DOUT + c4 * 4) =
                *(const float4*)(W + (size_t)(k0 + kk) * DOUT + c4 * 4);
        }
        __syncthreads();

#pragma unroll
        for (int kk = 0; kk < KB; kk++) {
            float4 b = *(const float4*)(Ws + kk * DOUT + cg * 4);
#pragma unroll
            for (int i = 0; i < RPT; i++) {
                float a = Hs[(rg * RPT + i) * KB + kk];
                acc[i][0] += a * b.x;
                acc[i][1] += a * b.y;
                acc[i][2] += a * b.z;
                acc[i][3] += a * b.w;
            }
        }
        __syncthreads();
    }

#pragma unroll
    for (int i = 0; i < RPT; i++) {
        int row = row0 + rg * RPT + i;
        if (row < N) {
            *(float4*)(C + (size_t)row * DOUT + cg * 4) =
                make_float4(acc[i][0], acc[i][1], acc[i][2], acc[i][3]);
        }
    }
}

// ---------------------------------------------------------------------------
// Init aggregation buffer with broadcast bias (folds "+ b" into the init)
// ---------------------------------------------------------------------------
template <int DOUT>
__global__ void init_bias_kernel(float* __restrict__ A, const float* __restrict__ b,
                                 int n4) {
    int i = blockIdx.x * blockDim.x + threadIdx.x;
    if (i >= n4) return;
    int c = i & (DOUT / 4 - 1);
    ((float4*)A)[i] = ((const float4*)b)[c];
}

// ---------------------------------------------------------------------------
// Edge scatter: A[dst] += S[src] * val   (one thread per edge x float4 chunk)
// Vector reduction red.global.add.v4.f32 (sm_90+) quarters atomic op count.
// ---------------------------------------------------------------------------
template <int DOUT>
__global__ void __launch_bounds__(256) scatter_kernel(const float* __restrict__ S,
                                                      const int* __restrict__ src,
                                                      const int* __restrict__ dst,
                                                      const float* __restrict__ val,
                                                      float* __restrict__ A, int E) {
    constexpr int C = DOUT / 4;
    int idx = blockIdx.x * blockDim.x + threadIdx.x;
    int e = idx / C;
    int c = idx % C;
    if (e >= E) return;

    int s  = __ldg(src + e);
    int d  = __ldg(dst + e);
    float v = __ldg(val + e);

    float4 m = *(const float4*)(S + (size_t)s * DOUT + c * 4);
    m.x *= v; m.y *= v; m.z *= v; m.w *= v;

    float* p = A + (size_t)d * DOUT + c * 4;
    asm volatile("red.global.add.v4.f32 [%0], {%1, %2, %3, %4};"
                 :: "l"(p), "f"(m.x), "f"(m.y), "f"(m.z), "f"(m.w)
                 : "memory");
}

// ---------------------------------------------------------------------------
// Launch
// ---------------------------------------------------------------------------
extern "C" void kernel_launch(void* const* d_in, const int* in_sizes, int n_in,
                              void* d_out, int out_size) {
    const float* x    = (const float*)d_in[0];
    const int*   esrc = (const int*)d_in[1];
    const int*   edst = (const int*)d_in[2];
    const float* eval = (const float*)d_in[3];
    const float* W1 = (const float*)d_in[4];
    const float* b1 = (const float*)d_in[5];
    const float* W2 = (const float*)d_in[6];
    const float* b2 = (const float*)d_in[7];
    const float* W3 = (const float*)d_in[8];
    const float* b3 = (const float*)d_in[9];
    const float* W4 = (const float*)d_in[10];
    const float* b4 = (const float*)d_in[11];
    float* out = (float*)d_out;

    float *S = nullptr, *A = nullptr;
    cudaGetSymbolAddress((void**)&S, g_S);
    cudaGetSymbolAddress((void**)&A, g_A);

    const int N = N_NODES;
    const int E = N_EDGES;
    const int gemm_grid = (N + 63) / 64;

    // ---- Layer 1: x(128) -> 128
    gemm_kernel<128, 128, false><<<gemm_grid, 256>>>(x, W1, S, N);
    {
        int n4 = N * 128 / 4;
        init_bias_kernel<128><<<(n4 + 255) / 256, 256>>>(A, b1, n4);
        int tot = E * (128 / 4);
        scatter_kernel<128><<<(tot + 255) / 256, 256>>>(S, esrc, edst, eval, A, E);
    }

    // ---- Layer 2: relu(A)(128) -> 128
    gemm_kernel<128, 128, true><<<gemm_grid, 256>>>(A, W2, S, N);
    {
        int n4 = N * 128 / 4;
        init_bias_kernel<128><<<(n4 + 255) / 256, 256>>>(A, b2, n4);
        int tot = E * (128 / 4);
        scatter_kernel<128><<<(tot + 255) / 256, 256>>>(S, esrc, edst, eval, A, E);
    }

    // ---- Layer 3: relu(A)(128) -> 64
    gemm_kernel<128, 64, true><<<gemm_grid, 256>>>(A, W3, S, N);
    {
        int n4 = N * 64 / 4;
        init_bias_kernel<64><<<(n4 + 255) / 256, 256>>>(A, b3, n4);
        int tot = E * (64 / 4);
        scatter_kernel<64><<<(tot + 255) / 256, 256>>>(S, esrc, edst, eval, A, E);
    }

    // ---- Layer 4: relu(A)(64) -> 32, scatter directly into d_out (init w/ b4)
    gemm_kernel<64, 32, true><<<gemm_grid, 256>>>(A, W4, S, N);
    {
        int n4 = N * 32 / 4;
        init_bias_kernel<32><<<(n4 + 255) / 256, 256>>>(out, b4, n4);
        int tot = E * (32 / 4);
        scatter_kernel<32><<<(tot + 255) / 256, 256>>>(S, esrc, edst, eval, out, E);
    }
}

// round 4
// speedup vs baseline: 1.3454x; 1.3454x over previous
#include <cuda_runtime.h>
#include <cuda_bf16.h>
#include <cstdint>
#include <cstddef>

#define N_NODES 50000
#define N_EDGES 800000

// Scratch (allocation-free rule: __device__ globals)
__device__ float g_S[(size_t)N_NODES * 128];   // support = h @ W
__device__ float g_A[(size_t)N_NODES * 128];   // aggregation target / next-layer input
__device__ int   g_off[N_NODES + 1];           // CSR row offsets (by dst)
__device__ int   g_cur[N_NODES];               // counters / running cursors
__device__ int   g_src_s[N_EDGES];             // src sorted by dst
__device__ float g_val_s[N_EDGES];             // val sorted by dst

// ---------------------------------------------------------------------------
// GEMM: C[N, DOUT] = act(H)[N, DIN] @ W[DIN, DOUT]   (relu fused on load)
// ---------------------------------------------------------------------------
template <int DIN, int DOUT, bool RELU>
__global__ void __launch_bounds__(256) gemm_kernel(const float* __restrict__ H,
                                                   const float* __restrict__ W,
                                                   float* __restrict__ C, int N) {
    constexpr int KB  = 32;
    constexpr int NC  = DOUT / 4;   // column groups (4 cols each)
    constexpr int NR  = 256 / NC;   // row groups
    constexpr int RPT = 64 / NR;    // rows per thread

    __shared__ float Hs[64 * KB];
    __shared__ float Ws[KB * DOUT];

    const int tid  = threadIdx.x;
    const int row0 = blockIdx.x * 64;
    const int cg   = tid % NC;
    const int rg   = tid / NC;

    float acc[RPT][4];
#pragma unroll
    for (int i = 0; i < RPT; i++) {
        acc[i][0] = 0.f; acc[i][1] = 0.f; acc[i][2] = 0.f; acc[i][3] = 0.f;
    }

    for (int k0 = 0; k0 < DIN; k0 += KB) {
#pragma unroll
        for (int t = tid; t < 64 * KB / 4; t += 256) {
            int r   = t >> 3;       // KB/4 = 8 float4 per row
            int kk4 = t & 7;
            int row = row0 + r;
            float4 v = make_float4(0.f, 0.f, 0.f, 0.f);
            if (row < N)
                v = *(const float4*)(H + (size_t)row * DIN + k0 + kk4 * 4);
            if (RELU) {
                v.x = fmaxf(v.x, 0.f); v.y = fmaxf(v.y, 0.f);
                v.z = fmaxf(v.z, 0.f); v.w = fmaxf(v.w, 0.f);
            }
            *(float4*)(Hs + r * KB + kk4 * 4) = v;
        }
#pragma unroll
        for (int t = tid; t < KB * NC; t += 256) {
            int kk = t / NC;
            int c4 = t % NC;
            *(float4*)(Ws + kk * DOUT + c4 * 4) =
                *(const float4*)(W + (size_t)(k0 + kk) * DOUT + c4 * 4);
        }
        __syncthreads();

#pragma unroll
        for (int kk = 0; kk < KB; kk++) {
            float4 b = *(const float4*)(Ws + kk * DOUT + cg * 4);
#pragma unroll
            for (int i = 0; i < RPT; i++) {
                float a = Hs[(rg * RPT + i) * KB + kk];
                acc[i][0] += a * b.x;
                acc[i][1] += a * b.y;
                acc[i][2] += a * b.z;
                acc[i][3] += a * b.w;
            }
        }
        __syncthreads();
    }

#pragma unroll
    for (int i = 0; i < RPT; i++) {
        int row = row0 + rg * RPT + i;
        if (row < N) {
            *(float4*)(C + (size_t)row * DOUT + cg * 4) =
                make_float4(acc[i][0], acc[i][1], acc[i][2], acc[i][3]);
        }
    }
}

// ---------------------------------------------------------------------------
// Counting sort by dst: histogram -> exclusive scan -> permute
// ---------------------------------------------------------------------------
__global__ void hist_kernel(const int* __restrict__ dst, int* __restrict__ cnt, int E) {
    int e = blockIdx.x * blockDim.x + threadIdx.x;
    if (e < E) atomicAdd(&cnt[dst[e]], 1);
}

// Single-block exclusive scan over n counts (reads cnt_cur, overwrites it with
// the exclusive prefix = running cursor base, writes off[0..n]).
__global__ void __launch_bounds__(1024) scan_kernel(int* __restrict__ cnt_cur,
                                                    int* __restrict__ off, int n) {
    __shared__ int wsum[32];
    __shared__ int carry;
    int tid = threadIdx.x;
    if (tid == 0) carry = 0;
    __syncthreads();
    for (int base = 0; base < n; base += 1024) {
        int i = base + tid;
        int v = (i < n) ? cnt_cur[i] : 0;
        int x = v;
#pragma unroll
        for (int o = 1; o < 32; o <<= 1) {
            int y = __shfl_up_sync(0xffffffffu, x, o);
            if ((tid & 31) >= o) x += y;
        }
        if ((tid & 31) == 31) wsum[tid >> 5] = x;
        __syncthreads();
        if (tid < 32) {
            int w = wsum[tid];
#pragma unroll
            for (int o = 1; o < 32; o <<= 1) {
                int y = __shfl_up_sync(0xffffffffu, w, o);
                if (tid >= o) w += y;
            }
            wsum[tid] = w;
        }
        __syncthreads();
        int excl = x - v + carry + ((tid >= 32) ? wsum[(tid >> 5) - 1] : 0);
        if (i < n) { off[i] = excl; cnt_cur[i] = excl; }
        __syncthreads();                    // everyone consumed carry & wsum
        if (tid == 0) carry += wsum[31];
        __syncthreads();
    }
    if (tid == 0) off[n] = carry;
}

__global__ void permute_kernel(const int* __restrict__ src, const int* __restrict__ dst,
                               const float* __restrict__ val, int* __restrict__ cur,
                               int* __restrict__ src_s, float* __restrict__ val_s, int E) {
    int e = blockIdx.x * blockDim.x + threadIdx.x;
    if (e >= E) return;
    int d = dst[e];
    int pos = atomicAdd(&cur[d], 1);
    src_s[pos] = src[e];
    val_s[pos] = val[e];
}

// ---------------------------------------------------------------------------
// Atomic-free aggregation: out[n] = bias + sum_{j in [off[n],off[n+1])}
//                                      S[src_s[j]] * val_s[j]
// D/4 lanes per node, accumulators in registers, single write per output row.
// ---------------------------------------------------------------------------
template <int D>
__global__ void __launch_bounds__(256) agg_kernel(const float* __restrict__ S,
                                                  const int* __restrict__ off,
                                                  const int* __restrict__ src_s,
                                                  const float* __restrict__ val_s,
                                                  const float* __restrict__ bias,
                                                  float* __restrict__ out, int N) {
    constexpr int L = D / 4;
    int t = blockIdx.x * blockDim.x + threadIdx.x;
    int node = t / L;
    int lane = t % L;
    if (node >= N) return;

    int beg = __ldg(off + node);
    int end = __ldg(off + node + 1);
    float4 acc = ((const float4*)bias)[lane];

    int j = beg;
    for (; j + 2 <= end; j += 2) {      // unroll x2 for load-level parallelism
        int   s0 = __ldg(src_s + j);
        int   s1 = __ldg(src_s + j + 1);
        float v0 = __ldg(val_s + j);
        float v1 = __ldg(val_s + j + 1);
        float4 m0 = *(const float4*)(S + (size_t)s0 * D + lane * 4);
        float4 m1 = *(const float4*)(S + (size_t)s1 * D + lane * 4);
        acc.x += v0 * m0.x; acc.y += v0 * m0.y; acc.z += v0 * m0.z; acc.w += v0 * m0.w;
        acc.x += v1 * m1.x; acc.y += v1 * m1.y; acc.z += v1 * m1.z; acc.w += v1 * m1.w;
    }
    if (j < end) {
        int   s0 = __ldg(src_s + j);
        float v0 = __ldg(val_s + j);
        float4 m0 = *(const float4*)(S + (size_t)s0 * D + lane * 4);
        acc.x += v0 * m0.x; acc.y += v0 * m0.y; acc.z += v0 * m0.z; acc.w += v0 * m0.w;
    }

    *(float4*)(out + (size_t)node * D + lane * 4) = acc;
}

// ---------------------------------------------------------------------------
// Launch
// ---------------------------------------------------------------------------
extern "C" void kernel_launch(void* const* d_in, const int* in_sizes, int n_in,
                              void* d_out, int out_size) {
    const float* x    = (const float*)d_in[0];
    const int*   esrc = (const int*)d_in[1];
    const int*   edst = (const int*)d_in[2];
    const float* eval = (const float*)d_in[3];
    const float* W1 = (const float*)d_in[4];
    const float* b1 = (const float*)d_in[5];
    const float* W2 = (const float*)d_in[6];
    const float* b2 = (const float*)d_in[7];
    const float* W3 = (const float*)d_in[8];
    const float* b3 = (const float*)d_in[9];
    const float* W4 = (const float*)d_in[10];
    const float* b4 = (const float*)d_in[11];
    float* out = (float*)d_out;

    float *S = nullptr, *A = nullptr;
    int *off = nullptr, *cur = nullptr, *src_s = nullptr;
    float *val_s = nullptr;
    cudaGetSymbolAddress((void**)&S, g_S);
    cudaGetSymbolAddress((void**)&A, g_A);
    cudaGetSymbolAddress((void**)&off, g_off);
    cudaGetSymbolAddress((void**)&cur, g_cur);
    cudaGetSymbolAddress((void**)&src_s, g_src_s);
    cudaGetSymbolAddress((void**)&val_s, g_val_s);

    const int N = N_NODES;
    const int E = N_EDGES;
    const int gemm_grid = (N + 63) / 64;

    // ---- Build CSR by dst (once; reused by all 4 layers) ----
    cudaMemsetAsync(cur, 0, N * sizeof(int));
    hist_kernel<<<(E + 255) / 256, 256>>>(edst, cur, E);
    scan_kernel<<<1, 1024>>>(cur, off, N);
    permute_kernel<<<(E + 255) / 256, 256>>>(esrc, edst, eval, cur, src_s, val_s, E);

    // ---- Layer 1: x(128) -> 128
    gemm_kernel<128, 128, false><<<gemm_grid, 256>>>(x, W1, S, N);
    agg_kernel<128><<<(N * 32 + 255) / 256, 256>>>(S, off, src_s, val_s, b1, A, N);

    // ---- Layer 2: relu(A)(128) -> 128
    gemm_kernel<128, 128, true><<<gemm_grid, 256>>>(A, W2, S, N);
    agg_kernel<128><<<(N * 32 + 255) / 256, 256>>>(S, off, src_s, val_s, b2, A, N);

    // ---- Layer 3: relu(A)(128) -> 64
    gemm_kernel<128, 64, true><<<gemm_grid, 256>>>(A, W3, S, N);
    agg_kernel<64><<<(N * 16 + 255) / 256, 256>>>(S, off, src_s, val_s, b3, A, N);

    // ---- Layer 4: relu(A)(64) -> 32, aggregate directly into d_out
    gemm_kernel<64, 32, true><<<gemm_grid, 256>>>(A, W4, S, N);
    agg_kernel<32><<<(N * 8 + 255) / 256, 256>>>(S, off, src_s, val_s, b4, out, N);
}